// round 14
// baseline (speedup 1.0000x reference)
#include <cuda_runtime.h>
#include <float.h>

#define VX 64
#define NB 8
#define NP 32
#define PE 32
#define EPSF 1e-8f
#define NQ 4                 // poly quarters per (b,row)
#define NPQ (NP / NQ)        // 8 polys per quarter

// Merge buffers (zero-initialized at load; each launch restores them to zero).
__device__ int g_comb[NB * VX * VX];    // float-as-int, atomicMax-merged masks
__device__ int g_count[NB * VX];        // per-(b,row) arrival counters

__device__ __forceinline__ float ex2_approx(float x) {
    float r; asm("ex2.approx.ftz.f32 %0, %1;" : "=f"(r) : "f"(x)); return r;
}
__device__ __forceinline__ float rcp_approx(float x) {
    float r; asm("rcp.approx.ftz.f32 %0, %1;" : "=f"(r) : "f"(x)); return r;
}

// 2048 blocks = (b, row, quarter), 128 threads = 4 warps.
// Each block: parity-mask SDF over its <=8 valid polys (critical warp ~1 poly),
// atomicMax partial row into g_comb; the last-arriving block of each (b,row)
// does the depth-masked z-expansion and resets the merge state.
__global__ __launch_bounds__(128, 8) void extrusion_kernel(
    const float* __restrict__ polygons,   // [B][N][P][2]
    const float* __restrict__ attributes, // [B][4]
    const float* __restrict__ validity,   // [B][N]
    float* __restrict__ out)              // [B][V][V][V]
{
    __shared__ __align__(16) float4 sA[NPQ * PE];   // x0, exi, syi, ey
    __shared__ __align__(16) float2 sC[NPQ * PE];   // ex, vy
    __shared__ __align__(16) float  sPartial[4][VX];
    __shared__ __align__(16) float  sComb[VX];
    __shared__ unsigned sParLo[NPQ], sParHi[NPQ];
    __shared__ int sIdx[NPQ];
    __shared__ int sV;
    __shared__ int sLast;

    const int bid = blockIdx.x;
    const int q   = bid & 3;             // low bits: mix quarters across SMs
    const int b   = (bid >> 2) & 7;
    const int row = bid >> 5;
    const int tid = threadIdx.x;
    const int cr  = b * VX + row;        // (b,row) group id
    const float py = (float)row * (1.0f / 63.0f);

    // ---- Phase 1a: validity compaction over this quarter's 8 polys ----
    if (tid < 32) {
        const bool valid = (tid < NPQ) &&
                           (validity[b * NP + q * NPQ + tid] >= 0.5f);
        const unsigned m = __ballot_sync(0xffffffffu, valid);
        if (valid) {
            const int pos = __popc(m & ((1u << tid) - 1u));
            sIdx[pos] = tid;              // local poly index 0..7
        }
        if (tid == 0) sV = __popc(m);
    }

    // ---- Phase 1b: edge precompute + parity masks ----
    // warp w (0..3), lane e: polys {w, w+4} (one poly's 32 edges per warp pass)
    const float2* pv = (const float2*)polygons + ((size_t)b * NP + q * NPQ) * PE;
    {
        const int w = tid >> 5;
        const int e = tid & 31;
        const int e1 = (e + 1) & 31;
        #pragma unroll
        for (int k = 0; k < 2; k++) {
            const int n = w + 4 * k;      // local poly
            const float2 v0 = pv[n * PE + e];
            const float2 v1 = pv[n * PE + e1];
            const float ex = v1.x - v0.x;
            const float ey = v1.y - v0.y;
            const float inv = rcp_approx(fmaf(ex, ex, fmaf(ey, ey, EPSF)));
            const float vy  = py - v0.y;
            sA[n * PE + e] = make_float4(v0.x, ex * inv, (vy * ey) * inv, ey);
            sC[n * PE + e] = make_float2(ex, vy);
            const bool ycr = (fminf(v0.y, v1.y) <= py) && (fmaxf(v0.y, v1.y) > py);
            const float interx = fmaf(ex, __fdividef(vy, ey + EPSF), v0.x);
            const float cxthr = ycr ? interx : -FLT_MAX;
            float t = fminf(fmaxf(cxthr * 63.0f, -1.0f), 65.0f);
            int idx = (int)ceilf(t);
            idx = max(0, min(64, idx));
            const unsigned long long m64 =
                (idx >= 64) ? ~0ull : ((1ull << idx) - 1ull);
            const unsigned lo = __reduce_xor_sync(0xffffffffu, (unsigned)m64);
            const unsigned hi = __reduce_xor_sync(0xffffffffu, (unsigned)(m64 >> 32));
            if (e == 0) { sParLo[n] = lo; sParHi[n] = hi; }
        }
    }
    __syncthreads();

    // ---- Phase 2: SDF + sigmoid + max; warp g takes compacted polys g, g+4 ----
    const int lane = tid & 31;
    const int g    = tid >> 5;
    const float pxa = (float)lane        * (1.0f / 63.0f);
    const float pxb = (float)(lane + 32) * (1.0f / 63.0f);
    const int nv = sV;

    float best_a = 0.0f, best_b = 0.0f;
    #pragma unroll 1
    for (int j = g; j < nv; j += 4) {      // typically 1 iteration
        const int n = sIdx[j];
        const unsigned sign_a = ((sParLo[n] >> lane) & 1u) << 31;
        const unsigned sign_b = ((sParHi[n] >> lane) & 1u) << 31;
        float min_a = FLT_MAX, min_b = FLT_MAX;
        const float4* A4 = sA + n * PE;
        const float2* C2 = sC + n * PE;
        #pragma unroll
        for (int e = 0; e < PE; e++) {
            const float4 a = A4[e];        // x0, exi, syi, ey
            const float2 c = C2[e];        // ex, vy
            const float vxa = pxa - a.x;
            const float vxb = pxb - a.x;
            const float ta = __saturatef(fmaf(vxa, a.y, a.z));
            const float tb = __saturatef(fmaf(vxb, a.y, a.z));
            const float dxa = fmaf(-ta, c.x, vxa);
            const float dxb = fmaf(-tb, c.x, vxb);
            const float dya = fmaf(-ta, a.w, c.y);
            const float dyb = fmaf(-tb, a.w, c.y);
            min_a = fminf(min_a, fmaf(dya, dya, dxa * dxa));
            min_b = fminf(min_b, fmaf(dyb, dyb, dxb * dxb));
        }
        const float sa = __uint_as_float(__float_as_uint(sqrtf(min_a)) ^ sign_a);
        const float sb = __uint_as_float(__float_as_uint(sqrtf(min_b)) ^ sign_b);
        // sigmoid(-100*s) = 1/(1 + 2^(144.27*s))
        best_a = fmaxf(best_a, rcp_approx(1.0f + ex2_approx(sa * 144.269504f)));
        best_b = fmaxf(best_b, rcp_approx(1.0f + ex2_approx(sb * 144.269504f)));
    }
    sPartial[g][lane]      = best_a;
    sPartial[g][lane + 32] = best_b;
    __syncthreads();

    // ---- Phase 3: 4-way reduce, REDG-merge into g_comb ----
    if (tid < VX) {
        const float m = fmaxf(fmaxf(sPartial[0][tid], sPartial[1][tid]),
                              fmaxf(sPartial[2][tid], sPartial[3][tid]));
        atomicMax(&g_comb[cr * VX + tid], __float_as_int(m));  // m >= 0
    }

    // ---- Phase 4: arrival protocol; 4th block expands and resets ----
    __threadfence();                       // publish my maxes before counting
    if (tid == 0) sLast = (atomicAdd(&g_count[cr], 1) == NQ - 1);
    __syncthreads();
    if (!sLast) return;

    __threadfence();                       // acquire: see all siblings' maxes
    if (tid < VX)
        sComb[tid] = __int_as_float(__ldcg(&g_comb[cr * VX + tid]));
    __syncthreads();

    int h = (int)floorf(attributes[b * 4 + 0] * (float)VX);
    h = max(1, min(VX, h));

    const float4* comb4 = (const float4*)sComb;
    float* out_base = out + (size_t)b * VX * VX * VX + (size_t)row * VX;
    const float4 zero4 = make_float4(0.f, 0.f, 0.f, 0.f);
    #pragma unroll
    for (int i = tid; i < VX * 16; i += 128) {   // 8 float4 per thread
        const int z = i >> 4;
        const int k = i & 15;
        ((float4*)(out_base + (size_t)z * VX * VX))[k] = (z < h) ? comb4[k] : zero4;
    }

    // reset merge state for the next (graph-replayed) launch
    if (tid < VX) g_comb[cr * VX + tid] = 0;
    if (tid == 0) g_count[cr] = 0;
}

extern "C" void kernel_launch(void* const* d_in, const int* in_sizes, int n_in,
                              void* d_out, int out_size) {
    const float* polygons   = (const float*)d_in[0];
    const float* attributes = (const float*)d_in[1];
    const float* validity   = (const float*)d_in[2];
    float* out = (float*)d_out;
    (void)in_sizes; (void)n_in; (void)out_size;

    extrusion_kernel<<<NB * VX * NQ, 128>>>(polygons, attributes, validity, out);
}

// round 16
// speedup vs baseline: 1.1532x; 1.1532x over previous
#include <cuda_runtime.h>
#include <float.h>

#define VX 64
#define NB 8
#define NP 32
#define PE 32
#define EPSF 1e-8f
#define NTHREADS 256
#define NWARPS 8

__device__ __forceinline__ float ex2_approx(float x) {
    float r; asm("ex2.approx.ftz.f32 %0, %1;" : "=f"(r) : "f"(x)); return r;
}
__device__ __forceinline__ float rcp_approx(float x) {
    float r; asm("rcp.approx.ftz.f32 %0, %1;" : "=f"(r) : "f"(x)); return r;
}

// Block: one (batch b, row y). 8 warps, 2 pixels/lane.
// Warp-autonomous pipeline: every warp ballots validity itself (no barrier),
// then precomputes ONLY the polys it will consume (lane e = edge e; vertex e+1
// via shfl, halving LDGs; parity mask via REDUX.XOR into uniform registers),
// syncwarp, and immediately runs the 32-edge distance loop on its own data.
// Exactly ONE block-wide barrier (final 8-way max). Precompute work ~ nv, not NP.
__global__ __launch_bounds__(NTHREADS, 4) void extrusion_kernel(
    const float* __restrict__ polygons,   // [B][N][P][2]
    const float* __restrict__ attributes, // [B][4]
    const float* __restrict__ validity,   // [B][N]
    float* __restrict__ out)              // [B][V][V][V]
{
    __shared__ __align__(16) float4 sA[NP * PE];   // x0, exi, syi, ey (slot = task j)
    __shared__ __align__(16) float2 sC[NP * PE];   // ex, vy
    __shared__ __align__(16) float  sPartial[NWARPS][VX];
    __shared__ __align__(16) float  sComb[VX];

    const int b   = blockIdx.x & 7;        // low bits: mix batches across SMs
    const int row = blockIdx.x >> 3;
    const int tid = threadIdx.x;
    const int lane = tid & 31;
    const int g    = tid >> 5;
    const float py = (float)row * (1.0f / 63.0f);

    // ---- Phase 0: h + early zero stores (independent of SDF, overlaps all) ----
    int h = (int)floorf(attributes[b * 4 + 0] * (float)VX);
    h = max(1, min(VX, h));
    float* out_base = out + (size_t)b * VX * VX * VX + (size_t)row * VX;
    const float4 zero4 = make_float4(0.f, 0.f, 0.f, 0.f);
    for (int i = h * 16 + tid; i < VX * 16; i += NTHREADS) {
        const int z = i >> 4;
        const int q = i & 15;
        ((float4*)(out_base + (size_t)z * VX * VX))[q] = zero4;
    }

    // ---- Per-warp validity ballot (broadcast LDG, no block barrier) ----
    const bool valid = validity[b * NP + lane] >= 0.5f;
    const unsigned vm = __ballot_sync(0xffffffffu, valid);
    const int nv  = __popc(vm);
    const int pos = __popc(vm & ((1u << lane) - 1u));   // rank among valid

    const float2* pv = (const float2*)polygons + (size_t)b * NP * PE;
    const float pxa = (float)lane        * (1.0f / 63.0f);
    const float pxb = (float)(lane + 32) * (1.0f / 63.0f);

    float best_a = 0.0f, best_b = 0.0f;

    #pragma unroll 1
    for (int j = g; j < nv; j += NWARPS) {
        // poly index for compacted task j (warp-uniform)
        const unsigned match = __ballot_sync(0xffffffffu, valid && (pos == j));
        const int n = __ffs(match) - 1;

        // ---- warp-private precompute: lane e handles edge e of poly n ----
        const float2 v0 = pv[n * PE + lane];
        const float v1x = __shfl_sync(0xffffffffu, v0.x, (lane + 1) & 31);
        const float v1y = __shfl_sync(0xffffffffu, v0.y, (lane + 1) & 31);
        const float ex = v1x - v0.x;
        const float ey = v1y - v0.y;
        const float inv = rcp_approx(fmaf(ex, ex, fmaf(ey, ey, EPSF)));
        const float vy  = py - v0.y;
        sA[j * PE + lane] = make_float4(v0.x, ex * inv, (vy * ey) * inv, ey);
        sC[j * PE + lane] = make_float2(ex, vy);
        // crossing threshold -> prefix bitmask over 64 pixel columns, XOR-reduce
        const bool ycr = (fminf(v0.y, v1y) <= py) && (fmaxf(v0.y, v1y) > py);
        const float interx = fmaf(ex, __fdividef(vy, ey + EPSF), v0.x);
        const float cxthr = ycr ? interx : -FLT_MAX;
        float t = fminf(fmaxf(cxthr * 63.0f, -1.0f), 65.0f);
        int idx = (int)ceilf(t);
        idx = max(0, min(64, idx));
        const unsigned long long m64 = (idx >= 64) ? ~0ull : ((1ull << idx) - 1ull);
        const unsigned lo = __reduce_xor_sync(0xffffffffu, (unsigned)m64);
        const unsigned hi = __reduce_xor_sync(0xffffffffu, (unsigned)(m64 >> 32));
        __syncwarp();                      // lanes' STS visible to whole warp

        // ---- consume: 32-edge distance loop, 2 pixels/lane ----
        const unsigned sign_a = ((lo >> lane) & 1u) << 31;
        const unsigned sign_b = ((hi >> lane) & 1u) << 31;
        float m0a = FLT_MAX, m1a = FLT_MAX, m0b = FLT_MAX, m1b = FLT_MAX;
        const float4* A4 = sA + j * PE;
        const float2* C2 = sC + j * PE;
        #pragma unroll
        for (int e = 0; e < PE; e += 2) {
            {
                const float4 a = A4[e];
                const float2 c = C2[e];
                const float vxa = pxa - a.x;
                const float vxb = pxb - a.x;
                const float ta = __saturatef(fmaf(vxa, a.y, a.z));
                const float tb = __saturatef(fmaf(vxb, a.y, a.z));
                const float dxa = fmaf(-ta, c.x, vxa);
                const float dxb = fmaf(-tb, c.x, vxb);
                const float dya = fmaf(-ta, a.w, c.y);
                const float dyb = fmaf(-tb, a.w, c.y);
                m0a = fminf(m0a, fmaf(dya, dya, dxa * dxa));
                m0b = fminf(m0b, fmaf(dyb, dyb, dxb * dxb));
            }
            {
                const float4 a = A4[e + 1];
                const float2 c = C2[e + 1];
                const float vxa = pxa - a.x;
                const float vxb = pxb - a.x;
                const float ta = __saturatef(fmaf(vxa, a.y, a.z));
                const float tb = __saturatef(fmaf(vxb, a.y, a.z));
                const float dxa = fmaf(-ta, c.x, vxa);
                const float dxb = fmaf(-tb, c.x, vxb);
                const float dya = fmaf(-ta, a.w, c.y);
                const float dyb = fmaf(-tb, a.w, c.y);
                m1a = fminf(m1a, fmaf(dya, dya, dxa * dxa));
                m1b = fminf(m1b, fmaf(dyb, dyb, dxb * dxb));
            }
        }
        const float mina = fminf(m0a, m1a);
        const float minb = fminf(m0b, m1b);
        const float sa = __uint_as_float(__float_as_uint(sqrtf(mina)) ^ sign_a);
        const float sb = __uint_as_float(__float_as_uint(sqrtf(minb)) ^ sign_b);
        // sigmoid(-100*s) = 1/(1 + 2^(144.27*s))
        best_a = fmaxf(best_a, rcp_approx(1.0f + ex2_approx(sa * 144.269504f)));
        best_b = fmaxf(best_b, rcp_approx(1.0f + ex2_approx(sb * 144.269504f)));
    }
    sPartial[g][lane]      = best_a;
    sPartial[g][lane + 32] = best_b;
    __syncthreads();                       // the ONE block-wide barrier

    // ---- 8-way max reduce -> combined row ----
    if (tid < VX) {
        float m = sPartial[0][tid];
        #pragma unroll
        for (int w = 1; w < NWARPS; w++) m = fmaxf(m, sPartial[w][tid]);
        sComb[tid] = m;
    }
    __syncthreads();

    // ---- store the z < h slabs ----
    const float4* comb4 = (const float4*)sComb;
    for (int i = tid; i < h * 16; i += NTHREADS) {
        const int z = i >> 4;
        const int q = i & 15;
        ((float4*)(out_base + (size_t)z * VX * VX))[q] = comb4[q];
    }
}

extern "C" void kernel_launch(void* const* d_in, const int* in_sizes, int n_in,
                              void* d_out, int out_size) {
    const float* polygons   = (const float*)d_in[0];
    const float* attributes = (const float*)d_in[1];
    const float* validity   = (const float*)d_in[2];
    float* out = (float*)d_out;
    (void)in_sizes; (void)n_in; (void)out_size;

    extrusion_kernel<<<NB * VX, NTHREADS>>>(polygons, attributes, validity, out);
}